// round 13
// baseline (speedup 1.0000x reference)
#include <cuda_runtime.h>
#include <cuda_fp16.h>
#include <cstdint>

#define NROWS 16384
#define INDIM 768
#define DD    128
#define BN    128
#define NJT   (NROWS / BN)
#define NITEMS (128 * NJT)

// ---------------- device scratch (no allocs allowed) ----------------
__device__ float g_wvfc[DD];
__device__ float g_bu_p;
__device__ float g_bu;
__device__ float g_wu[INDIM];
__device__ float g_bqk[256];
__device__ float g_u[NROWS];   // stores 0.5*u (sig*u = uh*tanh(0.5s) + uh)
__device__ __align__(16) __half g_xhi[NROWS * INDIM];
__device__ __align__(16) __half g_wTh[256 * INDIM];
__device__ __align__(16) __half g_qf[NROWS * DD];   // stores 0.5*q (tanh half-scale folded)
__device__ __align__(16) __half g_kf[NROWS * DD];

// ---------------- PTX helpers (base ISA only) -------------------------
__device__ __forceinline__ uint32_t smem_u32(const void* p) {
    uint32_t a;
    asm("{ .reg .u64 t; cvta.to.shared.u64 t, %1; cvt.u32.u64 %0, t; }" : "=r"(a) : "l"(p));
    return a;
}
#define CP_ASYNC16(dst, src) asm volatile("cp.async.cg.shared.global [%0], [%1], 16;" :: "r"(dst), "l"(src) : "memory")
#define CP_COMMIT()          asm volatile("cp.async.commit_group;" ::: "memory")
#define CP_WAIT(n)           asm volatile("cp.async.wait_group %0;" :: "n"(n) : "memory")

__device__ __forceinline__ void ldsm4(uint32_t* r, uint32_t addr) {
    asm volatile("ldmatrix.sync.aligned.m8n8.x4.shared.b16 {%0,%1,%2,%3}, [%4];"
                 : "=r"(r[0]), "=r"(r[1]), "=r"(r[2]), "=r"(r[3]) : "r"(addr));
}
__device__ __forceinline__ void mma_f16(float* c, const uint32_t* a, const uint32_t* b) {
    asm volatile("mma.sync.aligned.m16n8k16.row.col.f32.f16.f16.f32 "
                 "{%0,%1,%2,%3}, {%4,%5,%6,%7}, {%8,%9}, {%0,%1,%2,%3};"
                 : "+f"(c[0]), "+f"(c[1]), "+f"(c[2]), "+f"(c[3])
                 : "r"(a[0]), "r"(a[1]), "r"(a[2]), "r"(a[3]), "r"(b[0]), "r"(b[1]));
}
// pack two fp32 (already half-scaled) -> f16x2, packed tanh, unpack to fp32
__device__ __forceinline__ void tanh2(float s0, float s1, float& t0, float& t1) {
    asm("{\n\t"
        ".reg .b32 h, t;\n\t"
        ".reg .b16 lo, hi;\n\t"
        "cvt.rn.f16x2.f32 h, %3, %2;\n\t"   // hi = s1, lo = s0
        "tanh.approx.f16x2 t, h;\n\t"
        "mov.b32 {lo, hi}, t;\n\t"
        "cvt.f32.f16 %0, lo;\n\t"
        "cvt.f32.f16 %1, hi;\n\t"
        "}"
        : "=f"(t0), "=f"(t1) : "f"(s0), "f"(s1));
}

// ---------------- P1/P2: tiny weight precompute -----------------------
__global__ void k_p1(const float* __restrict__ W_qkv, const float* __restrict__ W_fc,
                     const float* __restrict__ b_qkv) {
    int d = threadIdx.x;
    float acc = 0.f;
    for (int e = 0; e < DD; e++) acc += W_qkv[d * 3 * DD + 2 * DD + e] * W_fc[e];
    g_wvfc[d] = acc;
    if (d == 0) {
        float b = 0.f;
        for (int e = 0; e < DD; e++) b += b_qkv[2 * DD + e] * W_fc[e];
        g_bu_p = b;
    }
}
// fused weight: W_token@W_qkv[:, :256], stored TRANSPOSED fp16
__global__ void k_p2(const float* __restrict__ W_token, const float* __restrict__ W_qkv) {
    __shared__ float wt[DD];
    int t = blockIdx.x, n = threadIdx.x;
    if (n < DD) wt[n] = W_token[t * DD + n];
    __syncthreads();
    float acc = 0.f;
    for (int d = 0; d < DD; d++) acc += wt[d] * W_qkv[d * 3 * DD + n];
    g_wTh[n * INDIM + t] = __float2half_rn(acc);
    if (n == 0) {
        float a = 0.f;
        for (int d = 0; d < DD; d++) a += wt[d] * g_wvfc[d];
        g_wu[t] = a;
    }
}
// biases + out = b_fc init (merged; also places k_attn at ncu launch slot 6)
__global__ void k_p3z(const float* __restrict__ b_token, const float* __restrict__ W_qkv,
                      const float* __restrict__ b_qkv, const float* __restrict__ b_fc,
                      float* __restrict__ out) {
    int n = threadIdx.x;
    if (blockIdx.x == 0) {
        float acc = 0.f;
        for (int d = 0; d < DD; d++) acc += b_token[d] * W_qkv[d * 3 * DD + n];
        g_bqk[n] = acc + b_qkv[n];
        if (n == 0) {
            float a = 0.f;
            for (int d = 0; d < DD; d++) a += b_token[d] * g_wvfc[d];
            g_bu = a + g_bu_p;
        }
    }
    out[blockIdx.x * 256 + n] = b_fc[0];
}

// ---------------- x -> fp16 split + u matvec (one warp per row) --------
__global__ __launch_bounds__(256) void k_xu(const float* __restrict__ x) {
    int row = blockIdx.x * 8 + (threadIdx.x >> 5);
    int lane = threadIdx.x & 31;
    const float* xr = x + (long)row * INDIM;
    __half* xh = g_xhi + (long)row * INDIM;
    float acc = 0.f;
#pragma unroll
    for (int i = 0; i < 6; i++) {
        int c = i * 128 + lane * 4;
        float4 v = *(const float4*)(xr + c);
        float4 wv = *(const float4*)(g_wu + c);
        acc += v.x * wv.x + v.y * wv.y + v.z * wv.z + v.w * wv.w;
        *(__half2*)(xh + c) = __floats2half2_rn(v.x, v.y);
        *(__half2*)(xh + c + 2) = __floats2half2_rn(v.z, v.w);
    }
#pragma unroll
    for (int off = 16; off; off >>= 1) acc += __shfl_xor_sync(0xFFFFFFFFu, acc, off);
    if (lane == 0) g_u[row] = 0.5f * (acc + g_bu);
}

// ---------------- projection GEMM (HMMA fp16, 1 pass per half) ---------
// BM=128, BN=128, BK=64. Stage: [xh 16K][wh 16K], double buffered.
#define PJ_STG  32768
#define PJ_SMEM (2 * PJ_STG)
__global__ __launch_bounds__(256, 2) void k_projh() {
    extern __shared__ char smem[];
    uint32_t sb = smem_u32(smem);
    int tid = threadIdx.x, lane = tid & 31, w = tid >> 5;
    int row0 = blockIdx.x * 128;
    int half = blockIdx.y;
    const __half* wh = g_wTh + (long)half * 128 * INDIM;

#define PJ_LOAD(buf, kc)                                                          \
    do {                                                                          \
        uint32_t base_ = sb + (buf) * PJ_STG;                                     \
        _Pragma("unroll")                                                         \
        for (int t_ = 0; t_ < 4; t_++) {                                          \
            int idx_ = t_ * 256 + tid;                                            \
            int r_ = idx_ >> 3, cu_ = idx_ & 7;                                   \
            uint32_t off_ = (uint32_t)r_ * 128u + (uint32_t)((cu_ ^ (r_ & 7)) << 4); \
            CP_ASYNC16(base_ + off_,         g_xhi + (long)(row0 + r_) * INDIM + (kc) + cu_ * 8); \
            CP_ASYNC16(base_ + 16384 + off_, wh + (long)r_ * INDIM + (kc) + cu_ * 8); \
        }                                                                         \
        CP_COMMIT();                                                              \
    } while (0)

    PJ_LOAD(0, 0);

    float acc[16][4];
#pragma unroll
    for (int nb = 0; nb < 16; nb++) {
        acc[nb][0] = 0.f; acc[nb][1] = 0.f; acc[nb][2] = 0.f; acc[nb][3] = 0.f;
    }

    int rA = 16 * w + (lane & 15);
    int cuA = lane >> 4;
    uint32_t rbA = (uint32_t)rA * 128u;
    int xA = rA & 7;
    int rB = (lane & 7) + ((lane & 16) >> 1);
    int cB = (lane >> 3) & 1;
    uint32_t uB = (uint32_t)rB * 128u;
    int xB = rB & 7;

    for (int s = 0; s < 12; s++) {
        if (s + 1 < 12) {
            PJ_LOAD((s + 1) & 1, (s + 1) * 64);
            CP_WAIT(1);
        } else {
            CP_WAIT(0);
        }
        __syncthreads();
        uint32_t base = sb + (s & 1) * PJ_STG;
#pragma unroll
        for (int kk = 0; kk < 4; kk++) {
            uint32_t Ah[4];
            uint32_t aoff = rbA + (uint32_t)(((kk * 2 + cuA) ^ xA) << 4);
            ldsm4(Ah, base + aoff);
            uint32_t coff = (uint32_t)(((kk * 2 + cB) ^ xB) << 4);
            uint32_t bh[8][4];
#pragma unroll
            for (int p = 0; p < 8; p++) ldsm4(bh[p], base + 16384 + p * 2048 + uB + coff);
#pragma unroll
            for (int p = 0; p < 8; p++) {
                mma_f16(acc[2 * p], Ah, &bh[p][0]);
                mma_f16(acc[2 * p + 1], Ah, &bh[p][2]);
            }
        }
        __syncthreads();
    }

    // epilogue: +bias; q additionally scaled by 0.5 (tanh half-scale folded)
    __half* dst = half ? g_kf : g_qf;
    float scale = half ? 1.0f : 0.5f;
    int r0 = row0 + 16 * w + (lane >> 2);
#pragma unroll
    for (int nb = 0; nb < 16; nb++) {
        int c = nb * 8 + (lane & 3) * 2;
        float b0 = g_bqk[half * 128 + c];
        float b1 = g_bqk[half * 128 + c + 1];
        *(__half2*)(dst + (long)r0 * DD + c) =
            __floats2half2_rn(scale * (acc[nb][0] + b0), scale * (acc[nb][1] + b1));
        *(__half2*)(dst + (long)(r0 + 8) * DD + c) =
            __floats2half2_rn(scale * (acc[nb][2] + b0), scale * (acc[nb][3] + b1));
    }
}

// ---------------- attention: persistent HMMA fp16 + f16x2 tanh --------
// K single fp16, double buffered 32KB each; u prefetched via cp.async.
#define KBUF   32768
#define SO_US  65536
#define AT_SMEM (SO_US + 1024)

__global__ __launch_bounds__(256, 1) void k_attn(float* __restrict__ out) {
    extern __shared__ char smem[];
    uint32_t sb = smem_u32(smem);
    int tid = threadIdx.x, lane = tid & 31, w = tid >> 5;

    int start = (int)((long)blockIdx.x * NITEMS / gridDim.x);
    int end = (int)((long)(blockIdx.x + 1) * NITEMS / gridDim.x);

    // preload K tile + u for first item into buf 0
    {
        int jt = start & (NJT - 1);
        const __half* sh = g_kf + (long)jt * BN * DD;
#pragma unroll
        for (int t = 0; t < 8; t++) {
            int idx = t * 256 + tid;
            int r = idx >> 4, cu = idx & 15;
            uint32_t off = (uint32_t)r * 256u + (uint32_t)((cu ^ (r & 7)) << 4);
            CP_ASYNC16(sb + off, sh + (long)r * DD + cu * 8);
        }
        if (tid < 32) CP_ASYNC16(sb + SO_US + tid * 16, g_u + jt * BN + tid * 4);
        CP_COMMIT();
    }

    int rB = (lane & 7) + ((lane & 16) >> 1);
    int cB = (lane >> 3) & 1;
    uint32_t uB = (uint32_t)rB * 256u;
    int xB = rB & 7;
    const int cl = (lane & 3) * 2;

    uint32_t Ah[8][4];
    float o0 = 0.f, o1 = 0.f;
    int it = -1;

    for (int idx = start; idx < end; idx++) {
        int b = (idx - start) & 1;
        __syncthreads();  // all warps done with buf b^1 (prev tile)
        if (idx + 1 < end) {
            int jn = (idx + 1) & (NJT - 1);
            uint32_t kb = sb + (b ^ 1) * KBUF;
            const __half* sh = g_kf + (long)jn * BN * DD;
#pragma unroll
            for (int t = 0; t < 8; t++) {
                int i2 = t * 256 + tid;
                int r = i2 >> 4, cu = i2 & 15;
                uint32_t off = (uint32_t)r * 256u + (uint32_t)((cu ^ (r & 7)) << 4);
                CP_ASYNC16(kb + off, sh + (long)r * DD + cu * 8);
            }
            if (tid < 32) CP_ASYNC16(sb + SO_US + (b ^ 1) * 512 + tid * 16, g_u + jn * BN + tid * 4);
            CP_COMMIT();
            CP_WAIT(1);
        } else {
            CP_WAIT(0);
        }
        __syncthreads();

        if ((idx >> 7) != it) {
            if (it >= 0) {
                o0 += __shfl_xor_sync(0xFFFFFFFFu, o0, 1);
                o0 += __shfl_xor_sync(0xFFFFFFFFu, o0, 2);
                o1 += __shfl_xor_sync(0xFFFFFFFFu, o1, 1);
                o1 += __shfl_xor_sync(0xFFFFFFFFu, o1, 2);
                if ((lane & 3) == 0) {
                    int r = it * 128 + 16 * w + (lane >> 2);
                    atomicAdd(out + r, o0);
                    atomicAdd(out + r + 8, o1);
                }
            }
            it = idx >> 7;
            o0 = 0.f; o1 = 0.f;
            const __half* qb = g_qf + ((long)it * 128 + 16 * w + (lane >> 2)) * DD + cl;
#pragma unroll
            for (int kk = 0; kk < 8; kk++) {
                Ah[kk][0] = *(const uint32_t*)(qb + kk * 16);
                Ah[kk][1] = *(const uint32_t*)(qb + 8 * DD + kk * 16);
                Ah[kk][2] = *(const uint32_t*)(qb + kk * 16 + 8);
                Ah[kk][3] = *(const uint32_t*)(qb + 8 * DD + kk * 16 + 8);
            }
        }

        uint32_t kb = sb + b * KBUF;
        float acc[16][4];
#pragma unroll
        for (int nb = 0; nb < 16; nb++) {
            acc[nb][0] = 0.f; acc[nb][1] = 0.f; acc[nb][2] = 0.f; acc[nb][3] = 0.f;
        }

#pragma unroll
        for (int kk = 0; kk < 8; kk++) {
            uint32_t coff = (uint32_t)(((kk * 2 + cB) ^ xB) << 4);
            uint32_t bh[8][4];
#pragma unroll
            for (int p = 0; p < 8; p++) ldsm4(bh[p], kb + p * 4096 + uB + coff);
#pragma unroll
            for (int p = 0; p < 8; p++) {
                mma_f16(acc[2 * p], Ah[kk], &bh[p][0]);
                mma_f16(acc[2 * p + 1], Ah[kk], &bh[p][2]);
            }
        }

        // sigmoid: sig*u = uh*tanh(0.5 s) + uh  (0.5 folded into q and g_u)
        // acc already holds 0.5*s; packed f16x2 tanh halves MUFU work.
        const float* Us = (const float*)(smem + SO_US + b * 512);
        float ts = 0.f;
#pragma unroll
        for (int nb = 0; nb < 16; nb++) {
            float2 u2 = *(const float2*)(Us + nb * 8 + cl);
            ts += u2.x + u2.y;
            float t0, t1, t2, t3;
            tanh2(acc[nb][0], acc[nb][1], t0, t1);
            tanh2(acc[nb][2], acc[nb][3], t2, t3);
            o0 = fmaf(t0, u2.x, o0); o0 = fmaf(t1, u2.y, o0);
            o1 = fmaf(t2, u2.x, o1); o1 = fmaf(t3, u2.y, o1);
        }
        o0 += ts;
        o1 += ts;
    }

    o0 += __shfl_xor_sync(0xFFFFFFFFu, o0, 1);
    o0 += __shfl_xor_sync(0xFFFFFFFFu, o0, 2);
    o1 += __shfl_xor_sync(0xFFFFFFFFu, o1, 1);
    o1 += __shfl_xor_sync(0xFFFFFFFFu, o1, 2);
    if (it >= 0 && (lane & 3) == 0) {
        int r = it * 128 + 16 * w + (lane >> 2);
        atomicAdd(out + r, o0);
        atomicAdd(out + r + 8, o1);
    }
}

// ---------------- launch ----------------------------------------------
extern "C" void kernel_launch(void* const* d_in, const int* in_sizes, int n_in,
                              void* d_out, int out_size) {
    const float* x       = (const float*)d_in[0];
    const float* W_token = (const float*)d_in[2];
    const float* b_token = (const float*)d_in[3];
    const float* W_qkv   = (const float*)d_in[4];
    const float* b_qkv   = (const float*)d_in[5];
    const float* W_fc    = (const float*)d_in[6];
    const float* b_fc    = (const float*)d_in[7];
    float* out = (float*)d_out;

    int nsm = 148;
    cudaDeviceGetAttribute(&nsm, cudaDevAttrMultiProcessorCount, 0);

    cudaFuncSetAttribute(k_attn, cudaFuncAttributeMaxDynamicSharedMemorySize, AT_SMEM);
    cudaFuncSetAttribute(k_projh, cudaFuncAttributeMaxDynamicSharedMemorySize, PJ_SMEM);

    k_p1<<<1, 128>>>(W_qkv, W_fc, b_qkv);                       // launch 1
    k_p2<<<768, 256>>>(W_token, W_qkv);                         // launch 2
    k_p3z<<<NROWS / 256, 256>>>(b_token, W_qkv, b_qkv, b_fc, out); // launch 3
    k_xu<<<NROWS / 8, 256>>>(x);                                // launch 4
    k_projh<<<dim3(128, 2), 256, PJ_SMEM>>>();                  // launch 5
    k_attn<<<nsm, 256, AT_SMEM>>>(out);                         // launch 6 (ncu -s 5)
}

// round 14
// speedup vs baseline: 1.0395x; 1.0395x over previous
#include <cuda_runtime.h>
#include <cuda_fp16.h>
#include <cstdint>

#define NROWS 16384
#define INDIM 768
#define DD    128
#define BN    128
#define NJT   (NROWS / BN)
#define NITEMS (128 * NJT)

// ---------------- device scratch (no allocs allowed) ----------------
__device__ float g_wvfc[DD];
__device__ float g_bu_p;
__device__ float g_bu;
__device__ float g_wu[INDIM];
__device__ float g_bqk[256];
__device__ float g_u[NROWS];   // stores 0.5*u (sig*u = uh*tanh(0.5s) + uh)
__device__ __align__(16) __half g_xhi[NROWS * INDIM];
__device__ __align__(16) __half g_wTh[256 * INDIM];
__device__ __align__(16) __half g_qf[NROWS * DD];   // stores 0.5*q (tanh half-scale folded)
__device__ __align__(16) __half g_kf[NROWS * DD];

// ---------------- PTX helpers (base ISA only) -------------------------
__device__ __forceinline__ uint32_t smem_u32(const void* p) {
    uint32_t a;
    asm("{ .reg .u64 t; cvta.to.shared.u64 t, %1; cvt.u32.u64 %0, t; }" : "=r"(a) : "l"(p));
    return a;
}
#define CP_ASYNC16(dst, src) asm volatile("cp.async.cg.shared.global [%0], [%1], 16;" :: "r"(dst), "l"(src) : "memory")
#define CP_COMMIT()          asm volatile("cp.async.commit_group;" ::: "memory")
#define CP_WAIT(n)           asm volatile("cp.async.wait_group %0;" :: "n"(n) : "memory")

__device__ __forceinline__ void ldsm4(uint32_t* r, uint32_t addr) {
    asm volatile("ldmatrix.sync.aligned.m8n8.x4.shared.b16 {%0,%1,%2,%3}, [%4];"
                 : "=r"(r[0]), "=r"(r[1]), "=r"(r[2]), "=r"(r[3]) : "r"(addr));
}
__device__ __forceinline__ void mma_f16(float* c, const uint32_t* a, const uint32_t* b) {
    asm volatile("mma.sync.aligned.m16n8k16.row.col.f32.f16.f16.f32 "
                 "{%0,%1,%2,%3}, {%4,%5,%6,%7}, {%8,%9}, {%0,%1,%2,%3};"
                 : "+f"(c[0]), "+f"(c[1]), "+f"(c[2]), "+f"(c[3])
                 : "r"(a[0]), "r"(a[1]), "r"(a[2]), "r"(a[3]), "r"(b[0]), "r"(b[1]));
}
__device__ __forceinline__ float tanh_ap(float x) {
    float r;
    asm("tanh.approx.f32 %0, %1;" : "=f"(r) : "f"(x));
    return r;
}

// ---------------- P1/P2: tiny weight precompute -----------------------
__global__ void k_p1(const float* __restrict__ W_qkv, const float* __restrict__ W_fc,
                     const float* __restrict__ b_qkv) {
    int d = threadIdx.x;
    float acc = 0.f;
    for (int e = 0; e < DD; e++) acc += W_qkv[d * 3 * DD + 2 * DD + e] * W_fc[e];
    g_wvfc[d] = acc;
    if (d == 0) {
        float b = 0.f;
        for (int e = 0; e < DD; e++) b += b_qkv[2 * DD + e] * W_fc[e];
        g_bu_p = b;
    }
}
// fused weight: W_token@W_qkv[:, :256], stored TRANSPOSED fp16
__global__ void k_p2(const float* __restrict__ W_token, const float* __restrict__ W_qkv) {
    __shared__ float wt[DD];
    int t = blockIdx.x, n = threadIdx.x;
    if (n < DD) wt[n] = W_token[t * DD + n];
    __syncthreads();
    float acc = 0.f;
    for (int d = 0; d < DD; d++) acc += wt[d] * W_qkv[d * 3 * DD + n];
    g_wTh[n * INDIM + t] = __float2half_rn(acc);
    if (n == 0) {
        float a = 0.f;
        for (int d = 0; d < DD; d++) a += wt[d] * g_wvfc[d];
        g_wu[t] = a;
    }
}
// biases + out = b_fc init
__global__ void k_p3z(const float* __restrict__ b_token, const float* __restrict__ W_qkv,
                      const float* __restrict__ b_qkv, const float* __restrict__ b_fc,
                      float* __restrict__ out) {
    int n = threadIdx.x;
    if (blockIdx.x == 0) {
        float acc = 0.f;
        for (int d = 0; d < DD; d++) acc += b_token[d] * W_qkv[d * 3 * DD + n];
        g_bqk[n] = acc + b_qkv[n];
        if (n == 0) {
            float a = 0.f;
            for (int d = 0; d < DD; d++) a += b_token[d] * g_wvfc[d];
            g_bu = a + g_bu_p;
        }
    }
    out[blockIdx.x * 256 + n] = b_fc[0];
}

// ---------------- x -> fp16 split + u matvec (one warp per row) --------
__global__ __launch_bounds__(256) void k_xu(const float* __restrict__ x) {
    int row = blockIdx.x * 8 + (threadIdx.x >> 5);
    int lane = threadIdx.x & 31;
    const float* xr = x + (long)row * INDIM;
    __half* xh = g_xhi + (long)row * INDIM;
    float acc = 0.f;
#pragma unroll
    for (int i = 0; i < 6; i++) {
        int c = i * 128 + lane * 4;
        float4 v = *(const float4*)(xr + c);
        float4 wv = *(const float4*)(g_wu + c);
        acc += v.x * wv.x + v.y * wv.y + v.z * wv.z + v.w * wv.w;
        *(__half2*)(xh + c) = __floats2half2_rn(v.x, v.y);
        *(__half2*)(xh + c + 2) = __floats2half2_rn(v.z, v.w);
    }
#pragma unroll
    for (int off = 16; off; off >>= 1) acc += __shfl_xor_sync(0xFFFFFFFFu, acc, off);
    if (lane == 0) g_u[row] = 0.5f * (acc + g_bu);
}

// ---------------- projection GEMM (HMMA fp16, 1 pass per half) ---------
#define PJ_STG  32768
#define PJ_SMEM (2 * PJ_STG)
__global__ __launch_bounds__(256, 1) void k_projh() {
    extern __shared__ char smem[];
    uint32_t sb = smem_u32(smem);
    int tid = threadIdx.x, lane = tid & 31, w = tid >> 5;
    int row0 = blockIdx.x * 128;
    int half = blockIdx.y;
    const __half* wh = g_wTh + (long)half * 128 * INDIM;

#define PJ_LOAD(buf, kc)                                                          \
    do {                                                                          \
        uint32_t base_ = sb + (buf) * PJ_STG;                                     \
        _Pragma("unroll")                                                         \
        for (int t_ = 0; t_ < 4; t_++) {                                          \
            int idx_ = t_ * 256 + tid;                                            \
            int r_ = idx_ >> 3, cu_ = idx_ & 7;                                   \
            uint32_t off_ = (uint32_t)r_ * 128u + (uint32_t)((cu_ ^ (r_ & 7)) << 4); \
            CP_ASYNC16(base_ + off_,         g_xhi + (long)(row0 + r_) * INDIM + (kc) + cu_ * 8); \
            CP_ASYNC16(base_ + 16384 + off_, wh + (long)r_ * INDIM + (kc) + cu_ * 8); \
        }                                                                         \
        CP_COMMIT();                                                              \
    } while (0)

    PJ_LOAD(0, 0);

    float acc[16][4];
#pragma unroll
    for (int nb = 0; nb < 16; nb++) {
        acc[nb][0] = 0.f; acc[nb][1] = 0.f; acc[nb][2] = 0.f; acc[nb][3] = 0.f;
    }

    int rA = 16 * w + (lane & 15);
    int cuA = lane >> 4;
    uint32_t rbA = (uint32_t)rA * 128u;
    int xA = rA & 7;
    int rB = (lane & 7) + ((lane & 16) >> 1);
    int cB = (lane >> 3) & 1;
    uint32_t uB = (uint32_t)rB * 128u;
    int xB = rB & 7;

    for (int s = 0; s < 12; s++) {
        if (s + 1 < 12) {
            PJ_LOAD((s + 1) & 1, (s + 1) * 64);
            CP_WAIT(1);
        } else {
            CP_WAIT(0);
        }
        __syncthreads();
        uint32_t base = sb + (s & 1) * PJ_STG;
#pragma unroll
        for (int kk = 0; kk < 4; kk++) {
            uint32_t Ah[4];
            uint32_t aoff = rbA + (uint32_t)(((kk * 2 + cuA) ^ xA) << 4);
            ldsm4(Ah, base + aoff);
            uint32_t coff = (uint32_t)(((kk * 2 + cB) ^ xB) << 4);
            uint32_t bh[8][4];
#pragma unroll
            for (int p = 0; p < 8; p++) ldsm4(bh[p], base + 16384 + p * 2048 + uB + coff);
#pragma unroll
            for (int p = 0; p < 8; p++) {
                mma_f16(acc[2 * p], Ah, &bh[p][0]);
                mma_f16(acc[2 * p + 1], Ah, &bh[p][2]);
            }
        }
        __syncthreads();
    }

    // epilogue: +bias; q additionally scaled by 0.5 (tanh half-scale folded)
    __half* dst = half ? g_kf : g_qf;
    float scale = half ? 1.0f : 0.5f;
    int r0 = row0 + 16 * w + (lane >> 2);
#pragma unroll
    for (int nb = 0; nb < 16; nb++) {
        int c = nb * 8 + (lane & 3) * 2;
        float b0 = g_bqk[half * 128 + c];
        float b1 = g_bqk[half * 128 + c + 1];
        *(__half2*)(dst + (long)r0 * DD + c) =
            __floats2half2_rn(scale * (acc[nb][0] + b0), scale * (acc[nb][1] + b1));
        *(__half2*)(dst + (long)(r0 + 8) * DD + c) =
            __floats2half2_rn(scale * (acc[nb][2] + b0), scale * (acc[nb][3] + b1));
    }
}

// ---------------- attention: persistent HMMA, 4x2 warp tiling ---------
// Warp tile = 32 rows x 64 cols: halves LDSM smem traffic (128KB/tile vs
// 256KB) so smem BW (1024 cyc) drops below the tensor floor (2048 cyc).
// K single fp16, double buffered 32KB each; u prefetched via cp.async.
#define KBUF   32768
#define SO_US  65536
#define AT_SMEM (SO_US + 1024)

__global__ __launch_bounds__(256, 1) void k_attn(float* __restrict__ out) {
    extern __shared__ char smem[];
    uint32_t sb = smem_u32(smem);
    int tid = threadIdx.x, lane = tid & 31, w = tid >> 5;
    int mw = w & 3;       // m position: rows mw*32 .. mw*32+31
    int nw = w >> 2;      // n position: cols nw*64 .. nw*64+63

    int start = (int)((long)blockIdx.x * NITEMS / gridDim.x);
    int end = (int)((long)(blockIdx.x + 1) * NITEMS / gridDim.x);

    // preload K tile + u for first item into buf 0
    {
        int jt = start & (NJT - 1);
        const __half* sh = g_kf + (long)jt * BN * DD;
#pragma unroll
        for (int t = 0; t < 8; t++) {
            int idx = t * 256 + tid;
            int r = idx >> 4, cu = idx & 15;
            uint32_t off = (uint32_t)r * 256u + (uint32_t)((cu ^ (r & 7)) << 4);
            CP_ASYNC16(sb + off, sh + (long)r * DD + cu * 8);
        }
        if (tid < 32) CP_ASYNC16(sb + SO_US + tid * 16, g_u + jt * BN + tid * 4);
        CP_COMMIT();
    }

    int rB = (lane & 7) + ((lane & 16) >> 1);
    int cB = (lane >> 3) & 1;
    uint32_t uB = (uint32_t)rB * 256u;
    int xB = rB & 7;
    const int cl = (lane & 3) * 2;

    uint32_t Ah[2][8][4];               // 2 m-frags x 8 ksteps
    float o00 = 0.f, o01 = 0.f, o10 = 0.f, o11 = 0.f;
    int it = -1;

    for (int idx = start; idx < end; idx++) {
        int b = (idx - start) & 1;
        __syncthreads();  // all warps done with buf b^1 (prev tile)
        if (idx + 1 < end) {
            int jn = (idx + 1) & (NJT - 1);
            uint32_t kb = sb + (b ^ 1) * KBUF;
            const __half* sh = g_kf + (long)jn * BN * DD;
#pragma unroll
            for (int t = 0; t < 8; t++) {
                int i2 = t * 256 + tid;
                int r = i2 >> 4, cu = i2 & 15;
                uint32_t off = (uint32_t)r * 256u + (uint32_t)((cu ^ (r & 7)) << 4);
                CP_ASYNC16(kb + off, sh + (long)r * DD + cu * 8);
            }
            if (tid < 32) CP_ASYNC16(sb + SO_US + (b ^ 1) * 512 + tid * 16, g_u + jn * BN + tid * 4);
            CP_COMMIT();
            CP_WAIT(1);
        } else {
            CP_WAIT(0);
        }
        __syncthreads();

        if ((idx >> 7) != it) {
            if (it >= 0) {
#pragma unroll
                for (int s = 1; s <= 2; s <<= 1) {
                    o00 += __shfl_xor_sync(0xFFFFFFFFu, o00, s);
                    o01 += __shfl_xor_sync(0xFFFFFFFFu, o01, s);
                    o10 += __shfl_xor_sync(0xFFFFFFFFu, o10, s);
                    o11 += __shfl_xor_sync(0xFFFFFFFFu, o11, s);
                }
                if ((lane & 3) == 0) {
                    int r = it * 128 + mw * 32 + (lane >> 2);
                    atomicAdd(out + r, o00);
                    atomicAdd(out + r + 8, o01);
                    atomicAdd(out + r + 16, o10);
                    atomicAdd(out + r + 24, o11);
                }
            }
            it = idx >> 7;
            o00 = 0.f; o01 = 0.f; o10 = 0.f; o11 = 0.f;
#pragma unroll
            for (int mf = 0; mf < 2; mf++) {
                const __half* qb =
                    g_qf + ((long)it * 128 + mw * 32 + mf * 16 + (lane >> 2)) * DD + cl;
#pragma unroll
                for (int kk = 0; kk < 8; kk++) {
                    Ah[mf][kk][0] = *(const uint32_t*)(qb + kk * 16);
                    Ah[mf][kk][1] = *(const uint32_t*)(qb + 8 * DD + kk * 16);
                    Ah[mf][kk][2] = *(const uint32_t*)(qb + kk * 16 + 8);
                    Ah[mf][kk][3] = *(const uint32_t*)(qb + 8 * DD + kk * 16 + 8);
                }
            }
        }

        uint32_t kb = sb + b * KBUF + nw * 16384;  // this warp's 64-col half (4x 16-row groups)
        float acc[2][8][4];
#pragma unroll
        for (int mf = 0; mf < 2; mf++)
#pragma unroll
            for (int nb = 0; nb < 8; nb++) {
                acc[mf][nb][0] = 0.f; acc[mf][nb][1] = 0.f;
                acc[mf][nb][2] = 0.f; acc[mf][nb][3] = 0.f;
            }

#pragma unroll
        for (int kk = 0; kk < 8; kk++) {
            uint32_t coff = (uint32_t)(((kk * 2 + cB) ^ xB) << 4);
            uint32_t bh[4][4];
#pragma unroll
            for (int p = 0; p < 4; p++) ldsm4(bh[p], kb + p * 4096 + uB + coff);
#pragma unroll
            for (int p = 0; p < 4; p++) {
                mma_f16(acc[0][2 * p], Ah[0][kk], &bh[p][0]);
                mma_f16(acc[0][2 * p + 1], Ah[0][kk], &bh[p][2]);
                mma_f16(acc[1][2 * p], Ah[1][kk], &bh[p][0]);
                mma_f16(acc[1][2 * p + 1], Ah[1][kk], &bh[p][2]);
            }
        }

        // sigmoid: sig*u = uh*tanh(0.5 s) + uh  (0.5 folded into q and g_u)
        const float* Us = (const float*)(smem + SO_US + b * 512) + nw * 64;
        float ts = 0.f;
#pragma unroll
        for (int nb = 0; nb < 8; nb++) {
            float2 u2 = *(const float2*)(Us + nb * 8 + cl);
            ts += u2.x + u2.y;
            float t0 = tanh_ap(acc[0][nb][0]);
            float t1 = tanh_ap(acc[0][nb][1]);
            float t2 = tanh_ap(acc[0][nb][2]);
            float t3 = tanh_ap(acc[0][nb][3]);
            o00 = fmaf(t0, u2.x, o00); o00 = fmaf(t1, u2.y, o00);
            o01 = fmaf(t2, u2.x, o01); o01 = fmaf(t3, u2.y, o01);
            t0 = tanh_ap(acc[1][nb][0]);
            t1 = tanh_ap(acc[1][nb][1]);
            t2 = tanh_ap(acc[1][nb][2]);
            t3 = tanh_ap(acc[1][nb][3]);
            o10 = fmaf(t0, u2.x, o10); o10 = fmaf(t1, u2.y, o10);
            o11 = fmaf(t2, u2.x, o11); o11 = fmaf(t3, u2.y, o11);
        }
        o00 += ts; o01 += ts; o10 += ts; o11 += ts;
    }

#pragma unroll
    for (int s = 1; s <= 2; s <<= 1) {
        o00 += __shfl_xor_sync(0xFFFFFFFFu, o00, s);
        o01 += __shfl_xor_sync(0xFFFFFFFFu, o01, s);
        o10 += __shfl_xor_sync(0xFFFFFFFFu, o10, s);
        o11 += __shfl_xor_sync(0xFFFFFFFFu, o11, s);
    }
    if (it >= 0 && (lane & 3) == 0) {
        int r = it * 128 + mw * 32 + (lane >> 2);
        atomicAdd(out + r, o00);
        atomicAdd(out + r + 8, o01);
        atomicAdd(out + r + 16, o10);
        atomicAdd(out + r + 24, o11);
    }
}

// ---------------- launch ----------------------------------------------
extern "C" void kernel_launch(void* const* d_in, const int* in_sizes, int n_in,
                              void* d_out, int out_size) {
    const float* x       = (const float*)d_in[0];
    const float* W_token = (const float*)d_in[2];
    const float* b_token = (const float*)d_in[3];
    const float* W_qkv   = (const float*)d_in[4];
    const float* b_qkv   = (const float*)d_in[5];
    const float* W_fc    = (const float*)d_in[6];
    const float* b_fc    = (const float*)d_in[7];
    float* out = (float*)d_out;

    int nsm = 148;
    cudaDeviceGetAttribute(&nsm, cudaDevAttrMultiProcessorCount, 0);

    cudaFuncSetAttribute(k_attn, cudaFuncAttributeMaxDynamicSharedMemorySize, AT_SMEM);
    cudaFuncSetAttribute(k_projh, cudaFuncAttributeMaxDynamicSharedMemorySize, PJ_SMEM);

    k_p1<<<1, 128>>>(W_qkv, W_fc, b_qkv);
    k_p2<<<768, 256>>>(W_token, W_qkv);
    k_p3z<<<NROWS / 256, 256>>>(b_token, W_qkv, b_qkv, b_fc, out);
    k_xu<<<NROWS / 8, 256>>>(x);
    k_projh<<<dim3(128, 2), 256, PJ_SMEM>>>();
    k_attn<<<nsm, 256, AT_SMEM>>>(out);
}